// round 4
// baseline (speedup 1.0000x reference)
#include <cuda_runtime.h>
#include <math.h>

#define EMB   1024
#define HD    64
#define NH    16
#define SEQ   2048
#define BATCH 2
#define MROWS (BATCH*SEQ)          // 4096
#define QKV_ELEMS (BATCH*NH*SEQ*HD)

// ---- scratch (allocation-free: __device__ globals) ----
__device__ float g_Q[QKV_ELEMS];
__device__ float g_K[QKV_ELEMS];
__device__ float g_V[QKV_ELEMS];
__device__ float g_O[QKV_ELEMS];
__device__ float g_partial[NH * 16];
__device__ float g_scale[NH];
__device__ float g_bias[EMB];

// ---- tf32 helpers ----
__device__ __forceinline__ float tf32r(float x) {
    unsigned u;
    asm("cvt.rna.tf32.f32 %0, %1;" : "=r"(u) : "f"(x));
    return __uint_as_float(u);
}
__device__ __forceinline__ unsigned fbits(float x) { return __float_as_uint(x); }

// D += A(16x8, row) * B(8x8, col) ; tf32 operands, fp32 accum
__device__ __forceinline__ void mma8(float c[4], const unsigned a[4],
                                     unsigned b0, unsigned b1) {
    asm volatile(
        "mma.sync.aligned.m16n8k8.row.col.f32.tf32.tf32.f32 "
        "{%0,%1,%2,%3},{%4,%5,%6,%7},{%8,%9},{%0,%1,%2,%3};"
        : "+f"(c[0]), "+f"(c[1]), "+f"(c[2]), "+f"(c[3])
        : "r"(a[0]), "r"(a[1]), "r"(a[2]), "r"(a[3]), "r"(b0), "r"(b1));
}

// ============================================================
// Kernel 1: QKV projection GEMM (tf32 tensor cores).
// C[4096,1024] = X @ W + bias; W stored [H,E,hd]; out -> [B,H,T,hd].
// Block 128x128, BK=16, 8 warps (2x4), warp tile 64x32.
// ============================================================
__global__ __launch_bounds__(256)
void qkv_gemm(const float* __restrict__ X,
              const float* __restrict__ Wq, const float* __restrict__ bq,
              const float* __restrict__ Wk, const float* __restrict__ bk,
              const float* __restrict__ Wv, const float* __restrict__ bv)
{
    const int z = blockIdx.z;
    const float* W    = (z == 0) ? Wq : (z == 1) ? Wk : Wv;
    const float* bias = (z == 0) ? bq : (z == 1) ? bk : bv;
    float* OUT        = (z == 0) ? g_Q : (z == 1) ? g_K : g_V;

    __shared__ float As[128][20];    // m-major, k padded 16->20
    __shared__ float Bs[16][136];    // k-major, n padded 128->136

    const int m0   = blockIdx.y * 128;
    const int n0   = blockIdx.x * 128;
    const int tid  = threadIdx.x;
    const int warp = tid >> 5;
    const int lane = tid & 31;
    const int lr   = lane >> 2;      // 0..7
    const int lc   = lane & 3;       // 0..3
    const int wm   = (warp >> 2) * 64;
    const int wn   = (warp & 3) * 32;

    float c[4][4][4];
    #pragma unroll
    for (int mt = 0; mt < 4; mt++)
        #pragma unroll
        for (int nt = 0; nt < 4; nt++)
            #pragma unroll
            for (int r = 0; r < 4; r++) c[mt][nt][r] = 0.f;

    for (int k0 = 0; k0 < EMB; k0 += 16) {
        // A tile: 128 rows x 16 k, m-major
        #pragma unroll
        for (int i = 0; i < 2; i++) {
            int f    = tid + i * 256;
            int arow = f >> 2;
            int ac   = (f & 3) * 4;
            float4 v = *(const float4*)&X[(size_t)(m0 + arow) * EMB + k0 + ac];
            As[arow][ac + 0] = tf32r(v.x);
            As[arow][ac + 1] = tf32r(v.y);
            As[arow][ac + 2] = tf32r(v.z);
            As[arow][ac + 3] = tf32r(v.w);
        }
        // B tile: 16 k x 128 n ; W element (k, c=(h,e)) at h*E*hd + k*hd + e
        #pragma unroll
        for (int i = 0; i < 2; i++) {
            int f    = tid + i * 256;
            int brow = f >> 5;
            int bc   = (f & 31) * 4;
            int cc   = n0 + bc;
            int hh   = cc >> 6;
            int e    = cc & 63;
            float4 v = *(const float4*)&W[(size_t)hh * (EMB * HD) + (size_t)(k0 + brow) * HD + e];
            Bs[brow][bc + 0] = tf32r(v.x);
            Bs[brow][bc + 1] = tf32r(v.y);
            Bs[brow][bc + 2] = tf32r(v.z);
            Bs[brow][bc + 3] = tf32r(v.w);
        }
        __syncthreads();

        #pragma unroll
        for (int kk = 0; kk < 2; kk++) {
            const int klo = kk * 8;
            unsigned a[4][4], bf[4][2];
            #pragma unroll
            for (int mt = 0; mt < 4; mt++) {
                int mr = wm + mt * 16 + lr;
                a[mt][0] = fbits(As[mr    ][klo + lc    ]);
                a[mt][1] = fbits(As[mr + 8][klo + lc    ]);
                a[mt][2] = fbits(As[mr    ][klo + lc + 4]);
                a[mt][3] = fbits(As[mr + 8][klo + lc + 4]);
            }
            #pragma unroll
            for (int nt = 0; nt < 4; nt++) {
                int nn = wn + nt * 8 + lr;
                bf[nt][0] = fbits(Bs[klo + lc    ][nn]);
                bf[nt][1] = fbits(Bs[klo + lc + 4][nn]);
            }
            #pragma unroll
            for (int mt = 0; mt < 4; mt++)
                #pragma unroll
                for (int nt = 0; nt < 4; nt++)
                    mma8(c[mt][nt], a[mt], bf[nt][0], bf[nt][1]);
        }
        __syncthreads();
    }

    // epilogue: remap to [B,H,T,hd], add bias
    #pragma unroll
    for (int mt = 0; mt < 4; mt++) {
        int row0 = m0 + wm + mt * 16 + lr;
        int row1 = row0 + 8;
        int b0i  = row0 >> 11, t0i = row0 & 2047;
        int b1i  = row1 >> 11, t1i = row1 & 2047;
        #pragma unroll
        for (int nt = 0; nt < 4; nt++) {
            int col = n0 + wn + nt * 8 + 2 * lc;
            int hh  = col >> 6;
            int e   = col & 63;
            float2 v0 = make_float2(c[mt][nt][0] + bias[col], c[mt][nt][1] + bias[col + 1]);
            float2 v1 = make_float2(c[mt][nt][2] + bias[col], c[mt][nt][3] + bias[col + 1]);
            *(float2*)&OUT[(size_t)((b0i * NH + hh) * SEQ + t0i) * HD + e] = v0;
            *(float2*)&OUT[(size_t)((b1i * NH + hh) * SEQ + t1i) * HD + e] = v1;
        }
    }
}

// ============================================================
// Kernel 2: flash attention per (b,h), tf32 tensor cores.
// 64 Q rows per block, 4 warps (each owns m16), KV tiles of 64.
// Q fragments register-resident; P reuses the K smem buffer.
// ============================================================
__global__ __launch_bounds__(128)
void attn_kernel(const float* __restrict__ mask)
{
    __shared__ float Ks[64][68];    // K tile [s][e], then P tile [m][s]
    __shared__ float Vs[64][72];    // V tile [s][e]

    const int mblk = blockIdx.x;
    const int h    = blockIdx.y;
    const int b    = blockIdx.z;
    const int tid  = threadIdx.x;
    const int warp = tid >> 5;
    const int lane = tid & 31;
    const int lr   = lane >> 2;
    const int lc   = lane & 3;
    const int wm   = warp * 16;     // warp's row base within 64

    const float* Q = g_Q + (size_t)(b * NH + h) * SEQ * HD;
    const float* K = g_K + (size_t)(b * NH + h) * SEQ * HD;
    const float* V = g_V + (size_t)(b * NH + h) * SEQ * HD;
    float*       O = g_O + (size_t)(b * NH + h) * SEQ * HD;

    const int t0 = mblk * 64;

    // Q fragments: m16 x k64 per warp (rows t0+wm+lr / +8)
    unsigned qa[8][4];
    {
        const float* qp0 = Q + (size_t)(t0 + wm + lr) * HD;
        const float* qp1 = qp0 + 8 * HD;
        #pragma unroll
        for (int k8 = 0; k8 < 8; k8++) {
            int e = k8 * 8;
            qa[k8][0] = fbits(tf32r(qp0[e + lc    ]));
            qa[k8][1] = fbits(tf32r(qp1[e + lc    ]));
            qa[k8][2] = fbits(tf32r(qp0[e + lc + 4]));
            qa[k8][3] = fbits(tf32r(qp1[e + lc + 4]));
        }
    }

    float m_i[2] = {-INFINITY, -INFINITY};
    float l_i[2] = {0.f, 0.f};
    float o[8][4];
    #pragma unroll
    for (int nt = 0; nt < 8; nt++)
        #pragma unroll
        for (int r = 0; r < 4; r++) o[nt][r] = 0.f;

    const float* mrowA = mask + (size_t)(t0 + wm + lr) * SEQ;
    const float* mrowB = mrowA + (size_t)8 * SEQ;

    for (int s0 = 0; s0 < SEQ; s0 += 64) {
        __syncthreads();   // prev PV reads of Ks/Vs complete

        // load K -> Ks[s][e], V -> Vs[s][e] (tf32-rounded)
        #pragma unroll
        for (int i = 0; i < 8; i++) {
            int f   = tid + i * 128;     // 0..1023
            int row = f >> 4;
            int col = (f & 15) * 4;
            float4 kv = *(const float4*)&K[(size_t)(s0 + row) * HD + col];
            Ks[row][col + 0] = tf32r(kv.x);
            Ks[row][col + 1] = tf32r(kv.y);
            Ks[row][col + 2] = tf32r(kv.z);
            Ks[row][col + 3] = tf32r(kv.w);
            float4 vv = *(const float4*)&V[(size_t)(s0 + row) * HD + col];
            Vs[row][col + 0] = tf32r(vv.x);
            Vs[row][col + 1] = tf32r(vv.y);
            Vs[row][col + 2] = tf32r(vv.z);
            Vs[row][col + 3] = tf32r(vv.w);
        }
        __syncthreads();

        // S = Q K^T : per-warp 16x64, 8 n-tiles
        float sc[8][4];
        #pragma unroll
        for (int nt = 0; nt < 8; nt++)
            #pragma unroll
            for (int r = 0; r < 4; r++) sc[nt][r] = 0.f;

        #pragma unroll
        for (int k8 = 0; k8 < 8; k8++) {
            int e = k8 * 8;
            #pragma unroll
            for (int nt = 0; nt < 8; nt++) {
                int s = nt * 8 + lr;
                unsigned b0 = fbits(Ks[s][e + lc    ]);
                unsigned b1 = fbits(Ks[s][e + lc + 4]);
                mma8(sc[nt], qa[k8], b0, b1);
            }
        }

        // scale + mask
        #pragma unroll
        for (int nt = 0; nt < 8; nt++) {
            float2 mv0 = *(const float2*)&mrowA[s0 + nt * 8 + 2 * lc];
            float2 mv1 = *(const float2*)&mrowB[s0 + nt * 8 + 2 * lc];
            sc[nt][0] = sc[nt][0] * 0.125f + mv0.x;
            sc[nt][1] = sc[nt][1] * 0.125f + mv0.y;
            sc[nt][2] = sc[nt][2] * 0.125f + mv1.x;
            sc[nt][3] = sc[nt][3] * 0.125f + mv1.y;
        }

        // online softmax, two row-halves per thread
        #pragma unroll
        for (int half = 0; half < 2; half++) {
            float rm = -INFINITY;
            #pragma unroll
            for (int nt = 0; nt < 8; nt++)
                rm = fmaxf(rm, fmaxf(sc[nt][2 * half], sc[nt][2 * half + 1]));
            rm = fmaxf(rm, __shfl_xor_sync(0xffffffffu, rm, 1));
            rm = fmaxf(rm, __shfl_xor_sync(0xffffffffu, rm, 2));
            float mnew = fmaxf(m_i[half], rm);
            float corr = __expf(m_i[half] - mnew);
            float rs = 0.f;
            #pragma unroll
            for (int nt = 0; nt < 8; nt++) {
                float p0 = __expf(sc[nt][2 * half    ] - mnew);
                float p1 = __expf(sc[nt][2 * half + 1] - mnew);
                sc[nt][2 * half] = p0;
                sc[nt][2 * half + 1] = p1;
                rs += p0 + p1;
            }
            rs += __shfl_xor_sync(0xffffffffu, rs, 1);
            rs += __shfl_xor_sync(0xffffffffu, rs, 2);
            l_i[half] = l_i[half] * corr + rs;
            m_i[half] = mnew;
            #pragma unroll
            for (int nt = 0; nt < 8; nt++) {
                o[nt][2 * half] *= corr;
                o[nt][2 * half + 1] *= corr;
            }
        }

        __syncthreads();   // all warps done reading Ks as K

        // store P (tf32) into Ks as [m][s]
        #pragma unroll
        for (int nt = 0; nt < 8; nt++) {
            *(float2*)&Ks[wm + lr    ][nt * 8 + 2 * lc] =
                make_float2(tf32r(sc[nt][0]), tf32r(sc[nt][1]));
            *(float2*)&Ks[wm + lr + 8][nt * 8 + 2 * lc] =
                make_float2(tf32r(sc[nt][2]), tf32r(sc[nt][3]));
        }
        __syncthreads();

        // O += P V
        #pragma unroll
        for (int k8 = 0; k8 < 8; k8++) {
            int s = k8 * 8;
            unsigned pa[4];
            pa[0] = fbits(Ks[wm + lr    ][s + lc    ]);
            pa[1] = fbits(Ks[wm + lr + 8][s + lc    ]);
            pa[2] = fbits(Ks[wm + lr    ][s + lc + 4]);
            pa[3] = fbits(Ks[wm + lr + 8][s + lc + 4]);
            #pragma unroll
            for (int nt = 0; nt < 8; nt++) {
                unsigned b0 = fbits(Vs[s + lc    ][nt * 8 + lr]);
                unsigned b1 = fbits(Vs[s + lc + 4][nt * 8 + lr]);
                mma8(o[nt], pa, b0, b1);
            }
        }
    }

    // finalize: divide by l, write raw O (norm folded in later)
    float inv0 = 1.f / l_i[0];
    float inv1 = 1.f / l_i[1];
    float* Op0 = O + (size_t)(t0 + wm + lr) * HD;
    float* Op1 = Op0 + 8 * HD;
    #pragma unroll
    for (int nt = 0; nt < 8; nt++) {
        *(float2*)&Op0[nt * 8 + 2 * lc] = make_float2(o[nt][0] * inv0, o[nt][1] * inv0);
        *(float2*)&Op1[nt * 8 + 2 * lc] = make_float2(o[nt][2] * inv1, o[nt][3] * inv1);
    }
}

// ============================================================
// Kernel 3: per-head norm partial sums (deterministic 2-stage reduce).
// ============================================================
__global__ __launch_bounds__(256)
void norm_partial()
{
    const int c   = blockIdx.x;
    const int h   = blockIdx.y;
    const int tid = threadIdx.x;
    const int bt  = c * 256 + tid;
    const int b   = bt >> 11;
    const int t   = bt & 2047;

    const float* row = g_O + (size_t)((b * NH + h) * SEQ + t) * HD;
    float ss = 0.f;
    #pragma unroll
    for (int i = 0; i < 16; i++) {
        float4 v = *(const float4*)&row[i * 4];
        ss += v.x * v.x + v.y * v.y + v.z * v.z + v.w * v.w;
    }
    float nrm = sqrtf(ss);

    __shared__ float red[256];
    red[tid] = nrm;
    __syncthreads();
    for (int s = 128; s > 0; s >>= 1) {
        if (tid < s) red[tid] += red[tid + s];
        __syncthreads();
    }
    if (tid == 0) g_partial[h * 16 + c] = red[0];
}

// ============================================================
// Kernel 4: finalize per-head scale and fused output bias.
// ============================================================
__global__ void finalize(const float* __restrict__ gate,
                         const float* __restrict__ b_o)
{
    const int tid = threadIdx.x;   // 1024 threads
    if (tid < NH) {
        float s = 0.f;
        #pragma unroll
        for (int c = 0; c < 16; c++) s += g_partial[tid * 16 + c];
        float denom = fmaxf(s / (float)MROWS, 1e-5f);
        float g = fminf(fmaxf(gate[tid], 0.f), 1.f);
        g_scale[tid] = g / (denom * (float)NH);
    }
    float bsum = 0.f;
    #pragma unroll
    for (int h = 0; h < NH; h++) {
        float g = fminf(fmaxf(gate[h], 0.f), 1.f);
        bsum += g * b_o[h * EMB + tid];
    }
    g_bias[tid] = bsum / (float)NH;
}

// ============================================================
// Kernel 5: output projection GEMM (tf32 tensor cores).
// A[r,k=(h,e)] = g_O[b,h,t,e] * g_scale[h]; B = W_o [1024,1024] linear.
// ============================================================
__global__ __launch_bounds__(256)
void out_gemm(const float* __restrict__ Wo, float* __restrict__ OUTP)
{
    __shared__ float As[128][20];
    __shared__ float Bs[16][136];

    const int m0   = blockIdx.y * 128;
    const int n0   = blockIdx.x * 128;
    const int tid  = threadIdx.x;
    const int warp = tid >> 5;
    const int lane = tid & 31;
    const int lr   = lane >> 2;
    const int lc   = lane & 3;
    const int wm   = (warp >> 2) * 64;
    const int wn   = (warp & 3) * 32;

    float c[4][4][4];
    #pragma unroll
    for (int mt = 0; mt < 4; mt++)
        #pragma unroll
        for (int nt = 0; nt < 4; nt++)
            #pragma unroll
            for (int r = 0; r < 4; r++) c[mt][nt][r] = 0.f;

    for (int k0 = 0; k0 < EMB; k0 += 16) {
        #pragma unroll
        for (int i = 0; i < 2; i++) {
            int f    = tid + i * 256;
            int arow = f >> 2;
            int ac   = (f & 3) * 4;
            int r    = m0 + arow;
            int k    = k0 + ac;
            int hh   = k >> 6;
            float s  = g_scale[hh];
            const float* src = &g_O[(size_t)(((r >> 11) * NH + hh) * SEQ + (r & 2047)) * HD + (k & 63)];
            float4 v = *(const float4*)src;
            As[arow][ac + 0] = tf32r(v.x * s);
            As[arow][ac + 1] = tf32r(v.y * s);
            As[arow][ac + 2] = tf32r(v.z * s);
            As[arow][ac + 3] = tf32r(v.w * s);
        }
        #pragma unroll
        for (int i = 0; i < 2; i++) {
            int f    = tid + i * 256;
            int brow = f >> 5;
            int bc   = (f & 31) * 4;
            float4 v = *(const float4*)&Wo[(size_t)(k0 + brow) * EMB + n0 + bc];
            Bs[brow][bc + 0] = tf32r(v.x);
            Bs[brow][bc + 1] = tf32r(v.y);
            Bs[brow][bc + 2] = tf32r(v.z);
            Bs[brow][bc + 3] = tf32r(v.w);
        }
        __syncthreads();

        #pragma unroll
        for (int kk = 0; kk < 2; kk++) {
            const int klo = kk * 8;
            unsigned a[4][4], bf[4][2];
            #pragma unroll
            for (int mt = 0; mt < 4; mt++) {
                int mr = wm + mt * 16 + lr;
                a[mt][0] = fbits(As[mr    ][klo + lc    ]);
                a[mt][1] = fbits(As[mr + 8][klo + lc    ]);
                a[mt][2] = fbits(As[mr    ][klo + lc + 4]);
                a[mt][3] = fbits(As[mr + 8][klo + lc + 4]);
            }
            #pragma unroll
            for (int nt = 0; nt < 4; nt++) {
                int nn = wn + nt * 8 + lr;
                bf[nt][0] = fbits(Bs[klo + lc    ][nn]);
                bf[nt][1] = fbits(Bs[klo + lc + 4][nn]);
            }
            #pragma unroll
            for (int mt = 0; mt < 4; mt++)
                #pragma unroll
                for (int nt = 0; nt < 4; nt++)
                    mma8(c[mt][nt], a[mt], bf[nt][0], bf[nt][1]);
        }
        __syncthreads();
    }

    #pragma unroll
    for (int mt = 0; mt < 4; mt++) {
        int row0 = m0 + wm + mt * 16 + lr;
        int row1 = row0 + 8;
        #pragma unroll
        for (int nt = 0; nt < 4; nt++) {
            int col = n0 + wn + nt * 8 + 2 * lc;
            float2 v0 = make_float2(c[mt][nt][0] + g_bias[col], c[mt][nt][1] + g_bias[col + 1]);
            float2 v1 = make_float2(c[mt][nt][2] + g_bias[col], c[mt][nt][3] + g_bias[col + 1]);
            *(float2*)&OUTP[(size_t)row0 * EMB + col] = v0;
            *(float2*)&OUTP[(size_t)row1 * EMB + col] = v1;
        }
    }
}

// ============================================================
extern "C" void kernel_launch(void* const* d_in, const int* in_sizes, int n_in,
                              void* d_out, int out_size)
{
    const float* X    = (const float*)d_in[0];
    const float* mask = (const float*)d_in[1];
    const float* Wq   = (const float*)d_in[2];
    const float* bq   = (const float*)d_in[3];
    const float* Wk   = (const float*)d_in[4];
    const float* bk   = (const float*)d_in[5];
    const float* Wv   = (const float*)d_in[6];
    const float* bv   = (const float*)d_in[7];
    const float* Wo   = (const float*)d_in[8];
    const float* bo   = (const float*)d_in[9];
    const float* gate = (const float*)d_in[10];
    float* out        = (float*)d_out;

    qkv_gemm    <<<dim3(EMB / 128, MROWS / 128, 3), 256>>>(X, Wq, bq, Wk, bk, Wv, bv);
    attn_kernel <<<dim3(SEQ / 64, NH, BATCH),       128>>>(mask);
    norm_partial<<<dim3(16, NH),                    256>>>();
    finalize    <<<1, EMB>>>(gate, bo);
    out_gemm    <<<dim3(EMB / 128, MROWS / 128),    256>>>(Wo, out);
}

// round 5
// speedup vs baseline: 1.0014x; 1.0014x over previous
#include <cuda_runtime.h>
#include <math.h>

#define EMB   1024
#define HD    64
#define NH    16
#define SEQ   2048
#define BATCH 2
#define MROWS (BATCH*SEQ)          // 4096
#define QKV_ELEMS (BATCH*NH*SEQ*HD)

// ---- scratch (allocation-free: __device__ globals) ----
__device__ float g_Q[QKV_ELEMS];
__device__ float g_K[QKV_ELEMS];
__device__ float g_V[QKV_ELEMS];
__device__ float g_O[QKV_ELEMS];
__device__ float g_partial[NH * 16];
__device__ float g_scale[NH];
__device__ float g_bias[EMB];

// ---- tf32 helpers ----
__device__ __forceinline__ float tf32r(float x) {
    unsigned u;
    asm("cvt.rna.tf32.f32 %0, %1;" : "=r"(u) : "f"(x));
    return __uint_as_float(u);
}
__device__ __forceinline__ unsigned fbits(float x) { return __float_as_uint(x); }

// D += A(16x8, row) * B(8x8, col) ; tf32 operands, fp32 accum
__device__ __forceinline__ void mma8(float c[4], const unsigned a[4],
                                     unsigned b0, unsigned b1) {
    asm volatile(
        "mma.sync.aligned.m16n8k8.row.col.f32.tf32.tf32.f32 "
        "{%0,%1,%2,%3},{%4,%5,%6,%7},{%8,%9},{%0,%1,%2,%3};"
        : "+f"(c[0]), "+f"(c[1]), "+f"(c[2]), "+f"(c[3])
        : "r"(a[0]), "r"(a[1]), "r"(a[2]), "r"(a[3]), "r"(b0), "r"(b1));
}

// ============================================================
// Kernel 1: QKV projection GEMM (tf32 tensor cores).
// C[4096,1024] = X @ W + bias; W stored [H,E,hd]; out -> [B,H,T,hd].
// Block 128x128, BK=16, 8 warps (2x4), warp tile 64x32.
// ============================================================
__global__ __launch_bounds__(256)
void qkv_gemm(const float* __restrict__ X,
              const float* __restrict__ Wq, const float* __restrict__ bq,
              const float* __restrict__ Wk, const float* __restrict__ bk,
              const float* __restrict__ Wv, const float* __restrict__ bv)
{
    const int z = blockIdx.z;
    const float* W    = (z == 0) ? Wq : (z == 1) ? Wk : Wv;
    const float* bias = (z == 0) ? bq : (z == 1) ? bk : bv;
    float* OUT        = (z == 0) ? g_Q : (z == 1) ? g_K : g_V;

    __shared__ float As[128][20];    // m-major, k padded 16->20
    __shared__ float Bs[16][136];    // k-major, n padded 128->136

    const int m0   = blockIdx.y * 128;
    const int n0   = blockIdx.x * 128;
    const int tid  = threadIdx.x;
    const int warp = tid >> 5;
    const int lane = tid & 31;
    const int lr   = lane >> 2;      // 0..7
    const int lc   = lane & 3;       // 0..3
    const int wm   = (warp >> 2) * 64;
    const int wn   = (warp & 3) * 32;

    float c[4][4][4];
    #pragma unroll
    for (int mt = 0; mt < 4; mt++)
        #pragma unroll
        for (int nt = 0; nt < 4; nt++)
            #pragma unroll
            for (int r = 0; r < 4; r++) c[mt][nt][r] = 0.f;

    for (int k0 = 0; k0 < EMB; k0 += 16) {
        // A tile: 128 rows x 16 k, m-major
        #pragma unroll
        for (int i = 0; i < 2; i++) {
            int f    = tid + i * 256;
            int arow = f >> 2;
            int ac   = (f & 3) * 4;
            float4 v = *(const float4*)&X[(size_t)(m0 + arow) * EMB + k0 + ac];
            As[arow][ac + 0] = tf32r(v.x);
            As[arow][ac + 1] = tf32r(v.y);
            As[arow][ac + 2] = tf32r(v.z);
            As[arow][ac + 3] = tf32r(v.w);
        }
        // B tile: 16 k x 128 n ; W element (k, c=(h,e)) at h*E*hd + k*hd + e
        #pragma unroll
        for (int i = 0; i < 2; i++) {
            int f    = tid + i * 256;
            int brow = f >> 5;
            int bc   = (f & 31) * 4;
            int cc   = n0 + bc;
            int hh   = cc >> 6;
            int e    = cc & 63;
            float4 v = *(const float4*)&W[(size_t)hh * (EMB * HD) + (size_t)(k0 + brow) * HD + e];
            Bs[brow][bc + 0] = tf32r(v.x);
            Bs[brow][bc + 1] = tf32r(v.y);
            Bs[brow][bc + 2] = tf32r(v.z);
            Bs[brow][bc + 3] = tf32r(v.w);
        }
        __syncthreads();

        #pragma unroll
        for (int kk = 0; kk < 2; kk++) {
            const int klo = kk * 8;
            unsigned a[4][4], bf[4][2];
            #pragma unroll
            for (int mt = 0; mt < 4; mt++) {
                int mr = wm + mt * 16 + lr;
                a[mt][0] = fbits(As[mr    ][klo + lc    ]);
                a[mt][1] = fbits(As[mr + 8][klo + lc    ]);
                a[mt][2] = fbits(As[mr    ][klo + lc + 4]);
                a[mt][3] = fbits(As[mr + 8][klo + lc + 4]);
            }
            #pragma unroll
            for (int nt = 0; nt < 4; nt++) {
                int nn = wn + nt * 8 + lr;
                bf[nt][0] = fbits(Bs[klo + lc    ][nn]);
                bf[nt][1] = fbits(Bs[klo + lc + 4][nn]);
            }
            #pragma unroll
            for (int mt = 0; mt < 4; mt++)
                #pragma unroll
                for (int nt = 0; nt < 4; nt++)
                    mma8(c[mt][nt], a[mt], bf[nt][0], bf[nt][1]);
        }
        __syncthreads();
    }

    // epilogue: remap to [B,H,T,hd], add bias
    #pragma unroll
    for (int mt = 0; mt < 4; mt++) {
        int row0 = m0 + wm + mt * 16 + lr;
        int row1 = row0 + 8;
        int b0i  = row0 >> 11, t0i = row0 & 2047;
        int b1i  = row1 >> 11, t1i = row1 & 2047;
        #pragma unroll
        for (int nt = 0; nt < 4; nt++) {
            int col = n0 + wn + nt * 8 + 2 * lc;
            int hh  = col >> 6;
            int e   = col & 63;
            float2 v0 = make_float2(c[mt][nt][0] + bias[col], c[mt][nt][1] + bias[col + 1]);
            float2 v1 = make_float2(c[mt][nt][2] + bias[col], c[mt][nt][3] + bias[col + 1]);
            *(float2*)&OUT[(size_t)((b0i * NH + hh) * SEQ + t0i) * HD + e] = v0;
            *(float2*)&OUT[(size_t)((b1i * NH + hh) * SEQ + t1i) * HD + e] = v1;
        }
    }
}

// ============================================================
// Kernel 2: flash attention per (b,h), tf32 tensor cores.
// 64 Q rows per block, 4 warps (each owns m16), KV tiles of 64.
// Q fragments register-resident; P reuses the K smem buffer.
// ============================================================
__global__ __launch_bounds__(128)
void attn_kernel(const float* __restrict__ mask)
{
    __shared__ float Ks[64][68];    // K tile [s][e], then P tile [m][s]
    __shared__ float Vs[64][72];    // V tile [s][e]

    const int mblk = blockIdx.x;
    const int h    = blockIdx.y;
    const int b    = blockIdx.z;
    const int tid  = threadIdx.x;
    const int warp = tid >> 5;
    const int lane = tid & 31;
    const int lr   = lane >> 2;
    const int lc   = lane & 3;
    const int wm   = warp * 16;     // warp's row base within 64

    const float* Q = g_Q + (size_t)(b * NH + h) * SEQ * HD;
    const float* K = g_K + (size_t)(b * NH + h) * SEQ * HD;
    const float* V = g_V + (size_t)(b * NH + h) * SEQ * HD;
    float*       O = g_O + (size_t)(b * NH + h) * SEQ * HD;

    const int t0 = mblk * 64;

    // Q fragments: m16 x k64 per warp (rows t0+wm+lr / +8)
    unsigned qa[8][4];
    {
        const float* qp0 = Q + (size_t)(t0 + wm + lr) * HD;
        const float* qp1 = qp0 + 8 * HD;
        #pragma unroll
        for (int k8 = 0; k8 < 8; k8++) {
            int e = k8 * 8;
            qa[k8][0] = fbits(tf32r(qp0[e + lc    ]));
            qa[k8][1] = fbits(tf32r(qp1[e + lc    ]));
            qa[k8][2] = fbits(tf32r(qp0[e + lc + 4]));
            qa[k8][3] = fbits(tf32r(qp1[e + lc + 4]));
        }
    }

    float m_i[2] = {-INFINITY, -INFINITY};
    float l_i[2] = {0.f, 0.f};
    float o[8][4];
    #pragma unroll
    for (int nt = 0; nt < 8; nt++)
        #pragma unroll
        for (int r = 0; r < 4; r++) o[nt][r] = 0.f;

    const float* mrowA = mask + (size_t)(t0 + wm + lr) * SEQ;
    const float* mrowB = mrowA + (size_t)8 * SEQ;

    for (int s0 = 0; s0 < SEQ; s0 += 64) {
        __syncthreads();   // prev PV reads of Ks/Vs complete

        // load K -> Ks[s][e], V -> Vs[s][e] (tf32-rounded)
        #pragma unroll
        for (int i = 0; i < 8; i++) {
            int f   = tid + i * 128;     // 0..1023
            int row = f >> 4;
            int col = (f & 15) * 4;
            float4 kv = *(const float4*)&K[(size_t)(s0 + row) * HD + col];
            Ks[row][col + 0] = tf32r(kv.x);
            Ks[row][col + 1] = tf32r(kv.y);
            Ks[row][col + 2] = tf32r(kv.z);
            Ks[row][col + 3] = tf32r(kv.w);
            float4 vv = *(const float4*)&V[(size_t)(s0 + row) * HD + col];
            Vs[row][col + 0] = tf32r(vv.x);
            Vs[row][col + 1] = tf32r(vv.y);
            Vs[row][col + 2] = tf32r(vv.z);
            Vs[row][col + 3] = tf32r(vv.w);
        }
        __syncthreads();

        // S = Q K^T : per-warp 16x64, 8 n-tiles
        float sc[8][4];
        #pragma unroll
        for (int nt = 0; nt < 8; nt++)
            #pragma unroll
            for (int r = 0; r < 4; r++) sc[nt][r] = 0.f;

        #pragma unroll
        for (int k8 = 0; k8 < 8; k8++) {
            int e = k8 * 8;
            #pragma unroll
            for (int nt = 0; nt < 8; nt++) {
                int s = nt * 8 + lr;
                unsigned b0 = fbits(Ks[s][e + lc    ]);
                unsigned b1 = fbits(Ks[s][e + lc + 4]);
                mma8(sc[nt], qa[k8], b0, b1);
            }
        }

        // scale + mask
        #pragma unroll
        for (int nt = 0; nt < 8; nt++) {
            float2 mv0 = *(const float2*)&mrowA[s0 + nt * 8 + 2 * lc];
            float2 mv1 = *(const float2*)&mrowB[s0 + nt * 8 + 2 * lc];
            sc[nt][0] = sc[nt][0] * 0.125f + mv0.x;
            sc[nt][1] = sc[nt][1] * 0.125f + mv0.y;
            sc[nt][2] = sc[nt][2] * 0.125f + mv1.x;
            sc[nt][3] = sc[nt][3] * 0.125f + mv1.y;
        }

        // online softmax, two row-halves per thread
        #pragma unroll
        for (int half = 0; half < 2; half++) {
            float rm = -INFINITY;
            #pragma unroll
            for (int nt = 0; nt < 8; nt++)
                rm = fmaxf(rm, fmaxf(sc[nt][2 * half], sc[nt][2 * half + 1]));
            rm = fmaxf(rm, __shfl_xor_sync(0xffffffffu, rm, 1));
            rm = fmaxf(rm, __shfl_xor_sync(0xffffffffu, rm, 2));
            float mnew = fmaxf(m_i[half], rm);
            float corr = __expf(m_i[half] - mnew);
            float rs = 0.f;
            #pragma unroll
            for (int nt = 0; nt < 8; nt++) {
                float p0 = __expf(sc[nt][2 * half    ] - mnew);
                float p1 = __expf(sc[nt][2 * half + 1] - mnew);
                sc[nt][2 * half] = p0;
                sc[nt][2 * half + 1] = p1;
                rs += p0 + p1;
            }
            rs += __shfl_xor_sync(0xffffffffu, rs, 1);
            rs += __shfl_xor_sync(0xffffffffu, rs, 2);
            l_i[half] = l_i[half] * corr + rs;
            m_i[half] = mnew;
            #pragma unroll
            for (int nt = 0; nt < 8; nt++) {
                o[nt][2 * half] *= corr;
                o[nt][2 * half + 1] *= corr;
            }
        }

        __syncthreads();   // all warps done reading Ks as K

        // store P (tf32) into Ks as [m][s]
        #pragma unroll
        for (int nt = 0; nt < 8; nt++) {
            *(float2*)&Ks[wm + lr    ][nt * 8 + 2 * lc] =
                make_float2(tf32r(sc[nt][0]), tf32r(sc[nt][1]));
            *(float2*)&Ks[wm + lr + 8][nt * 8 + 2 * lc] =
                make_float2(tf32r(sc[nt][2]), tf32r(sc[nt][3]));
        }
        __syncthreads();

        // O += P V
        #pragma unroll
        for (int k8 = 0; k8 < 8; k8++) {
            int s = k8 * 8;
            unsigned pa[4];
            pa[0] = fbits(Ks[wm + lr    ][s + lc    ]);
            pa[1] = fbits(Ks[wm + lr + 8][s + lc    ]);
            pa[2] = fbits(Ks[wm + lr    ][s + lc + 4]);
            pa[3] = fbits(Ks[wm + lr + 8][s + lc + 4]);
            #pragma unroll
            for (int nt = 0; nt < 8; nt++) {
                unsigned b0 = fbits(Vs[s + lc    ][nt * 8 + lr]);
                unsigned b1 = fbits(Vs[s + lc + 4][nt * 8 + lr]);
                mma8(o[nt], pa, b0, b1);
            }
        }
    }

    // finalize: divide by l, write raw O (norm folded in later)
    float inv0 = 1.f / l_i[0];
    float inv1 = 1.f / l_i[1];
    float* Op0 = O + (size_t)(t0 + wm + lr) * HD;
    float* Op1 = Op0 + 8 * HD;
    #pragma unroll
    for (int nt = 0; nt < 8; nt++) {
        *(float2*)&Op0[nt * 8 + 2 * lc] = make_float2(o[nt][0] * inv0, o[nt][1] * inv0);
        *(float2*)&Op1[nt * 8 + 2 * lc] = make_float2(o[nt][2] * inv1, o[nt][3] * inv1);
    }
}

// ============================================================
// Kernel 3: per-head norm partial sums (deterministic 2-stage reduce).
// ============================================================
__global__ __launch_bounds__(256)
void norm_partial()
{
    const int c   = blockIdx.x;
    const int h   = blockIdx.y;
    const int tid = threadIdx.x;
    const int bt  = c * 256 + tid;
    const int b   = bt >> 11;
    const int t   = bt & 2047;

    const float* row = g_O + (size_t)((b * NH + h) * SEQ + t) * HD;
    float ss = 0.f;
    #pragma unroll
    for (int i = 0; i < 16; i++) {
        float4 v = *(const float4*)&row[i * 4];
        ss += v.x * v.x + v.y * v.y + v.z * v.z + v.w * v.w;
    }
    float nrm = sqrtf(ss);

    __shared__ float red[256];
    red[tid] = nrm;
    __syncthreads();
    for (int s = 128; s > 0; s >>= 1) {
        if (tid < s) red[tid] += red[tid + s];
        __syncthreads();
    }
    if (tid == 0) g_partial[h * 16 + c] = red[0];
}

// ============================================================
// Kernel 4: finalize per-head scale and fused output bias.
// ============================================================
__global__ void finalize(const float* __restrict__ gate,
                         const float* __restrict__ b_o)
{
    const int tid = threadIdx.x;   // 1024 threads
    if (tid < NH) {
        float s = 0.f;
        #pragma unroll
        for (int c = 0; c < 16; c++) s += g_partial[tid * 16 + c];
        float denom = fmaxf(s / (float)MROWS, 1e-5f);
        float g = fminf(fmaxf(gate[tid], 0.f), 1.f);
        g_scale[tid] = g / (denom * (float)NH);
    }
    float bsum = 0.f;
    #pragma unroll
    for (int h = 0; h < NH; h++) {
        float g = fminf(fmaxf(gate[h], 0.f), 1.f);
        bsum += g * b_o[h * EMB + tid];
    }
    g_bias[tid] = bsum / (float)NH;
}

// ============================================================
// Kernel 5: output projection GEMM (tf32 tensor cores).
// A[r,k=(h,e)] = g_O[b,h,t,e] * g_scale[h]; B = W_o [1024,1024] linear.
// ============================================================
__global__ __launch_bounds__(256)
void out_gemm(const float* __restrict__ Wo, float* __restrict__ OUTP)
{
    __shared__ float As[128][20];
    __shared__ float Bs[16][136];

    const int m0   = blockIdx.y * 128;
    const int n0   = blockIdx.x * 128;
    const int tid  = threadIdx.x;
    const int warp = tid >> 5;
    const int lane = tid & 31;
    const int lr   = lane >> 2;
    const int lc   = lane & 3;
    const int wm   = (warp >> 2) * 64;
    const int wn   = (warp & 3) * 32;

    float c[4][4][4];
    #pragma unroll
    for (int mt = 0; mt < 4; mt++)
        #pragma unroll
        for (int nt = 0; nt < 4; nt++)
            #pragma unroll
            for (int r = 0; r < 4; r++) c[mt][nt][r] = 0.f;

    for (int k0 = 0; k0 < EMB; k0 += 16) {
        #pragma unroll
        for (int i = 0; i < 2; i++) {
            int f    = tid + i * 256;
            int arow = f >> 2;
            int ac   = (f & 3) * 4;
            int r    = m0 + arow;
            int k    = k0 + ac;
            int hh   = k >> 6;
            float s  = g_scale[hh];
            const float* src = &g_O[(size_t)(((r >> 11) * NH + hh) * SEQ + (r & 2047)) * HD + (k & 63)];
            float4 v = *(const float4*)src;
            As[arow][ac + 0] = tf32r(v.x * s);
            As[arow][ac + 1] = tf32r(v.y * s);
            As[arow][ac + 2] = tf32r(v.z * s);
            As[arow][ac + 3] = tf32r(v.w * s);
        }
        #pragma unroll
        for (int i = 0; i < 2; i++) {
            int f    = tid + i * 256;
            int brow = f >> 5;
            int bc   = (f & 31) * 4;
            float4 v = *(const float4*)&Wo[(size_t)(k0 + brow) * EMB + n0 + bc];
            Bs[brow][bc + 0] = tf32r(v.x);
            Bs[brow][bc + 1] = tf32r(v.y);
            Bs[brow][bc + 2] = tf32r(v.z);
            Bs[brow][bc + 3] = tf32r(v.w);
        }
        __syncthreads();

        #pragma unroll
        for (int kk = 0; kk < 2; kk++) {
            const int klo = kk * 8;
            unsigned a[4][4], bf[4][2];
            #pragma unroll
            for (int mt = 0; mt < 4; mt++) {
                int mr = wm + mt * 16 + lr;
                a[mt][0] = fbits(As[mr    ][klo + lc    ]);
                a[mt][1] = fbits(As[mr + 8][klo + lc    ]);
                a[mt][2] = fbits(As[mr    ][klo + lc + 4]);
                a[mt][3] = fbits(As[mr + 8][klo + lc + 4]);
            }
            #pragma unroll
            for (int nt = 0; nt < 4; nt++) {
                int nn = wn + nt * 8 + lr;
                bf[nt][0] = fbits(Bs[klo + lc    ][nn]);
                bf[nt][1] = fbits(Bs[klo + lc + 4][nn]);
            }
            #pragma unroll
            for (int mt = 0; mt < 4; mt++)
                #pragma unroll
                for (int nt = 0; nt < 4; nt++)
                    mma8(c[mt][nt], a[mt], bf[nt][0], bf[nt][1]);
        }
        __syncthreads();
    }

    #pragma unroll
    for (int mt = 0; mt < 4; mt++) {
        int row0 = m0 + wm + mt * 16 + lr;
        int row1 = row0 + 8;
        #pragma unroll
        for (int nt = 0; nt < 4; nt++) {
            int col = n0 + wn + nt * 8 + 2 * lc;
            float2 v0 = make_float2(c[mt][nt][0] + g_bias[col], c[mt][nt][1] + g_bias[col + 1]);
            float2 v1 = make_float2(c[mt][nt][2] + g_bias[col], c[mt][nt][3] + g_bias[col + 1]);
            *(float2*)&OUTP[(size_t)row0 * EMB + col] = v0;
            *(float2*)&OUTP[(size_t)row1 * EMB + col] = v1;
        }
    }
}

// ============================================================
extern "C" void kernel_launch(void* const* d_in, const int* in_sizes, int n_in,
                              void* d_out, int out_size)
{
    const float* X    = (const float*)d_in[0];
    const float* mask = (const float*)d_in[1];
    const float* Wq   = (const float*)d_in[2];
    const float* bq   = (const float*)d_in[3];
    const float* Wk   = (const float*)d_in[4];
    const float* bk   = (const float*)d_in[5];
    const float* Wv   = (const float*)d_in[6];
    const float* bv   = (const float*)d_in[7];
    const float* Wo   = (const float*)d_in[8];
    const float* bo   = (const float*)d_in[9];
    const float* gate = (const float*)d_in[10];
    float* out        = (float*)d_out;

    qkv_gemm    <<<dim3(EMB / 128, MROWS / 128, 3), 256>>>(X, Wq, bq, Wk, bk, Wv, bv);
    attn_kernel <<<dim3(SEQ / 64, NH, BATCH),       128>>>(mask);
    norm_partial<<<dim3(16, NH),                    256>>>();
    finalize    <<<1, EMB>>>(gate, bo);
    out_gemm    <<<dim3(EMB / 128, MROWS / 128),    256>>>(Wo, out);
}

// round 8
// speedup vs baseline: 1.5982x; 1.5959x over previous
#include <cuda_runtime.h>
#include <cuda_fp16.h>
#include <math.h>
#include <cstdint>

#define EMB   1024
#define HD    64
#define NH    16
#define SEQ   2048
#define BATCH 2
#define MROWS (BATCH*SEQ)          // 4096
#define QKV_ELEMS (BATCH*NH*SEQ*HD)

// ---- scratch (allocation-free: __device__ globals) ----
__device__ __half g_Q[QKV_ELEMS];
__device__ __half g_K[QKV_ELEMS];
__device__ __half g_V[QKV_ELEMS];
__device__ float  g_O[QKV_ELEMS];
__device__ float  g_partial[NH * 16];
__device__ float  g_scale[NH];
__device__ float  g_bias[EMB];

// ---- helpers ----
__device__ __forceinline__ uint32_t h2(float a, float b) {
    __half2 v = __floats2half2_rn(a, b);
    return *(uint32_t*)&v;
}
__device__ __forceinline__ uint32_t smem_u32(const void* p) {
    uint32_t a;
    asm("{ .reg .u64 t; cvta.to.shared.u64 t, %1; cvt.u32.u64 %0, t; }" : "=r"(a) : "l"(p));
    return a;
}
__device__ __forceinline__ void ldsm_x4(uint32_t& r0, uint32_t& r1, uint32_t& r2, uint32_t& r3,
                                        const void* p) {
    uint32_t a = smem_u32(p);
    asm volatile("ldmatrix.sync.aligned.m8n8.x4.shared.b16 {%0,%1,%2,%3},[%4];"
                 : "=r"(r0), "=r"(r1), "=r"(r2), "=r"(r3) : "r"(a));
}
__device__ __forceinline__ void ldsm_x4t(uint32_t& r0, uint32_t& r1, uint32_t& r2, uint32_t& r3,
                                         const void* p) {
    uint32_t a = smem_u32(p);
    asm volatile("ldmatrix.sync.aligned.m8n8.x4.trans.shared.b16 {%0,%1,%2,%3},[%4];"
                 : "=r"(r0), "=r"(r1), "=r"(r2), "=r"(r3) : "r"(a));
}
// D += A(16x16) * B(16x8); fp16 in, fp32 accum
__device__ __forceinline__ void mma16(float c[4], const uint32_t a[4],
                                      uint32_t b0, uint32_t b1) {
    asm volatile(
        "mma.sync.aligned.m16n8k16.row.col.f32.f16.f16.f32 "
        "{%0,%1,%2,%3},{%4,%5,%6,%7},{%8,%9},{%0,%1,%2,%3};"
        : "+f"(c[0]), "+f"(c[1]), "+f"(c[2]), "+f"(c[3])
        : "r"(a[0]), "r"(a[1]), "r"(a[2]), "r"(a[3]), "r"(b0), "r"(b1));
}

// ============================================================
// Kernel 1: QKV projection GEMM (fp16 mma + ldmatrix).
// ============================================================
__global__ __launch_bounds__(256)
void qkv_gemm(const float* __restrict__ X,
              const float* __restrict__ Wq, const float* __restrict__ bq,
              const float* __restrict__ Wk, const float* __restrict__ bk,
              const float* __restrict__ Wv, const float* __restrict__ bv)
{
    const int z = blockIdx.z;
    const float* W    = (z == 0) ? Wq : (z == 1) ? Wk : Wv;
    const float* bias = (z == 0) ? bq : (z == 1) ? bk : bv;
    __half* OUT       = (z == 0) ? g_Q : (z == 1) ? g_K : g_V;

    __shared__ __half As[128][40];    // m-major, k 32 + pad 8
    __shared__ __half Bs[32][136];    // k-major, n 128 + pad 8

    const int m0   = blockIdx.y * 128;
    const int n0   = blockIdx.x * 128;
    const int tid  = threadIdx.x;
    const int warp = tid >> 5;
    const int lane = tid & 31;
    const int lr   = lane >> 2;
    const int lc   = lane & 3;
    const int wm   = (warp >> 2) * 64;
    const int wn   = (warp & 3) * 32;
    const int lrow = (lane & 7) + (lane & 8);       // ldmatrix row-in-16
    const int lcol = (lane >> 1) & 8;               // ldmatrix col offset

    float c[4][4][4];
    #pragma unroll
    for (int mt = 0; mt < 4; mt++)
        #pragma unroll
        for (int nt = 0; nt < 4; nt++)
            #pragma unroll
            for (int r = 0; r < 4; r++) c[mt][nt][r] = 0.f;

    for (int k0 = 0; k0 < EMB; k0 += 32) {
        // A tile: 128 x 32
        #pragma unroll
        for (int i = 0; i < 4; i++) {
            int f    = tid + i * 256;
            int arow = f >> 3;
            int ac   = (f & 7) * 4;
            float4 v = *(const float4*)&X[(size_t)(m0 + arow) * EMB + k0 + ac];
            *(uint2*)&As[arow][ac] = make_uint2(h2(v.x, v.y), h2(v.z, v.w));
        }
        // B tile: 32 x 128 ; W element (k, c=(h,e)) at h*E*hd + k*hd + e
        #pragma unroll
        for (int i = 0; i < 4; i++) {
            int f    = tid + i * 256;
            int brow = f >> 5;
            int bc   = (f & 31) * 4;
            int cc   = n0 + bc;
            int hh   = cc >> 6;
            int e    = cc & 63;
            float4 v = *(const float4*)&W[(size_t)hh * (EMB * HD) + (size_t)(k0 + brow) * HD + e];
            *(uint2*)&Bs[brow][bc] = make_uint2(h2(v.x, v.y), h2(v.z, v.w));
        }
        __syncthreads();

        #pragma unroll
        for (int st = 0; st < 2; st++) {
            const int klo = st * 16;
            uint32_t a[4][4], bfr[2][4];
            #pragma unroll
            for (int mt = 0; mt < 4; mt++)
                ldsm_x4(a[mt][0], a[mt][1], a[mt][2], a[mt][3],
                        &As[wm + mt * 16 + lrow][klo + lcol]);
            #pragma unroll
            for (int p = 0; p < 2; p++)
                ldsm_x4t(bfr[p][0], bfr[p][1], bfr[p][2], bfr[p][3],
                         &Bs[klo + lrow][wn + p * 16 + lcol]);
            #pragma unroll
            for (int mt = 0; mt < 4; mt++)
                #pragma unroll
                for (int nt = 0; nt < 4; nt++)
                    mma16(c[mt][nt], a[mt], bfr[nt >> 1][(nt & 1) * 2],
                          bfr[nt >> 1][(nt & 1) * 2 + 1]);
        }
        __syncthreads();
    }

    // epilogue: remap to [B,H,T,hd] fp16, add bias
    #pragma unroll
    for (int mt = 0; mt < 4; mt++) {
        int row0 = m0 + wm + mt * 16 + lr;
        int row1 = row0 + 8;
        int b0i  = row0 >> 11, t0i = row0 & 2047;
        int b1i  = row1 >> 11, t1i = row1 & 2047;
        #pragma unroll
        for (int nt = 0; nt < 4; nt++) {
            int col = n0 + wn + nt * 8 + 2 * lc;
            int hh  = col >> 6;
            int e   = col & 63;
            uint32_t v0 = h2(c[mt][nt][0] + bias[col], c[mt][nt][1] + bias[col + 1]);
            uint32_t v1 = h2(c[mt][nt][2] + bias[col], c[mt][nt][3] + bias[col + 1]);
            *(uint32_t*)&OUT[(size_t)((b0i * NH + hh) * SEQ + t0i) * HD + e] = v0;
            *(uint32_t*)&OUT[(size_t)((b1i * NH + hh) * SEQ + t1i) * HD + e] = v1;
        }
    }
}

// ============================================================
// Kernel 2: flash attention per (b,h), fp16 mma + ldmatrix.
// ============================================================
__global__ __launch_bounds__(128)
void attn_kernel(const float* __restrict__ mask)
{
    __shared__ __half Ks[64][72];
    __shared__ __half Vs[64][72];

    const int mblk = blockIdx.x;
    const int h    = blockIdx.y;
    const int b    = blockIdx.z;
    const int tid  = threadIdx.x;
    const int warp = tid >> 5;
    const int lane = tid & 31;
    const int lr   = lane >> 2;
    const int lc   = lane & 3;
    const int wm   = warp * 16;
    const int lrow = (lane & 7) + (lane & 8);
    const int lcol = (lane >> 1) & 8;

    const __half* Q = g_Q + (size_t)(b * NH + h) * SEQ * HD;
    const __half* K = g_K + (size_t)(b * NH + h) * SEQ * HD;
    const __half* V = g_V + (size_t)(b * NH + h) * SEQ * HD;
    float*        O = g_O + (size_t)(b * NH + h) * SEQ * HD;

    const int t0 = mblk * 64;

    // Q fragments: 4 x k16 per warp (rows t0+wm+lr / +8), direct from gmem fp16
    uint32_t qa[4][4];
    {
        const __half* qp0 = Q + (size_t)(t0 + wm + lr) * HD;
        const __half* qp1 = qp0 + 8 * HD;
        #pragma unroll
        for (int q = 0; q < 4; q++) {
            int e = q * 16;
            qa[q][0] = *(const uint32_t*)&qp0[e + 2 * lc];
            qa[q][1] = *(const uint32_t*)&qp1[e + 2 * lc];
            qa[q][2] = *(const uint32_t*)&qp0[e + 2 * lc + 8];
            qa[q][3] = *(const uint32_t*)&qp1[e + 2 * lc + 8];
        }
    }

    float m_i[2] = {-INFINITY, -INFINITY};
    float l_i[2] = {0.f, 0.f};
    float o[8][4];
    #pragma unroll
    for (int nt = 0; nt < 8; nt++)
        #pragma unroll
        for (int r = 0; r < 4; r++) o[nt][r] = 0.f;

    const float* mrowA = mask + (size_t)(t0 + wm + lr) * SEQ;
    const float* mrowB = mrowA + (size_t)8 * SEQ;

    for (int s0 = 0; s0 < SEQ; s0 += 64) {
        __syncthreads();   // prev iter's smem reads complete

        // load K,V tiles (fp16, 8 halves = 16B per access)
        #pragma unroll
        for (int i = 0; i < 4; i++) {
            int f   = tid + i * 128;
            int row = f >> 3;
            int col = (f & 7) * 8;
            *(uint4*)&Ks[row][col] = *(const uint4*)&K[(size_t)(s0 + row) * HD + col];
            *(uint4*)&Vs[row][col] = *(const uint4*)&V[(size_t)(s0 + row) * HD + col];
        }
        __syncthreads();

        // S = Q K^T : per-warp 16x64
        float sc[8][4];
        #pragma unroll
        for (int nt = 0; nt < 8; nt++)
            #pragma unroll
            for (int r = 0; r < 4; r++) sc[nt][r] = 0.f;

        #pragma unroll
        for (int q = 0; q < 4; q++) {
            #pragma unroll
            for (int p = 0; p < 4; p++) {
                // Ks stored [s][e] = [n][k]; non-trans ldmatrix:
                //   r0 = (s0-7 , e0-7), r1 = (s8-15, e0-7),
                //   r2 = (s0-7 , e8-15), r3 = (s8-15, e8-15)
                // => b-pairs (k advances within a pair): (r0,r2) and (r1,r3)
                uint32_t r0, r1, r2, r3;
                ldsm_x4(r0, r1, r2, r3, &Ks[p * 16 + lrow][q * 16 + lcol]);
                mma16(sc[2 * p],     qa[q], r0, r2);
                mma16(sc[2 * p + 1], qa[q], r1, r3);
            }
        }

        // scale + mask
        #pragma unroll
        for (int nt = 0; nt < 8; nt++) {
            float2 mv0 = *(const float2*)&mrowA[s0 + nt * 8 + 2 * lc];
            float2 mv1 = *(const float2*)&mrowB[s0 + nt * 8 + 2 * lc];
            sc[nt][0] = sc[nt][0] * 0.125f + mv0.x;
            sc[nt][1] = sc[nt][1] * 0.125f + mv0.y;
            sc[nt][2] = sc[nt][2] * 0.125f + mv1.x;
            sc[nt][3] = sc[nt][3] * 0.125f + mv1.y;
        }

        // online softmax, two row-halves per thread
        #pragma unroll
        for (int half = 0; half < 2; half++) {
            float rm = -INFINITY;
            #pragma unroll
            for (int nt = 0; nt < 8; nt++)
                rm = fmaxf(rm, fmaxf(sc[nt][2 * half], sc[nt][2 * half + 1]));
            rm = fmaxf(rm, __shfl_xor_sync(0xffffffffu, rm, 1));
            rm = fmaxf(rm, __shfl_xor_sync(0xffffffffu, rm, 2));
            float mnew = fmaxf(m_i[half], rm);
            float corr = __expf(m_i[half] - mnew);
            float rs = 0.f;
            #pragma unroll
            for (int nt = 0; nt < 8; nt++) {
                float p0 = __expf(sc[nt][2 * half    ] - mnew);
                float p1 = __expf(sc[nt][2 * half + 1] - mnew);
                sc[nt][2 * half] = p0;
                sc[nt][2 * half + 1] = p1;
                rs += p0 + p1;
            }
            rs += __shfl_xor_sync(0xffffffffu, rs, 1);
            rs += __shfl_xor_sync(0xffffffffu, rs, 2);
            l_i[half] = l_i[half] * corr + rs;
            m_i[half] = mnew;
            #pragma unroll
            for (int nt = 0; nt < 8; nt++) {
                o[nt][2 * half] *= corr;
                o[nt][2 * half + 1] *= corr;
            }
        }

        // O += P V ; P taken straight from sc registers (C-frag == A-frag layout)
        #pragma unroll
        for (int q = 0; q < 4; q++) {
            uint32_t pa[4];
            pa[0] = h2(sc[2 * q][0], sc[2 * q][1]);
            pa[1] = h2(sc[2 * q][2], sc[2 * q][3]);
            pa[2] = h2(sc[2 * q + 1][0], sc[2 * q + 1][1]);
            pa[3] = h2(sc[2 * q + 1][2], sc[2 * q + 1][3]);
            #pragma unroll
            for (int p = 0; p < 4; p++) {
                // Vs stored [s][e] = [k][n]; trans ldmatrix: k advances r0->r1
                uint32_t b0a, b1a, b0b, b1b;
                ldsm_x4t(b0a, b1a, b0b, b1b, &Vs[q * 16 + lrow][p * 16 + lcol]);
                mma16(o[2 * p],     pa, b0a, b1a);
                mma16(o[2 * p + 1], pa, b0b, b1b);
            }
        }
    }

    // finalize: divide by l, write raw O fp32 (norm folded in later)
    float inv0 = 1.f / l_i[0];
    float inv1 = 1.f / l_i[1];
    float* Op0 = O + (size_t)(t0 + wm + lr) * HD;
    float* Op1 = Op0 + 8 * HD;
    #pragma unroll
    for (int nt = 0; nt < 8; nt++) {
        *(float2*)&Op0[nt * 8 + 2 * lc] = make_float2(o[nt][0] * inv0, o[nt][1] * inv0);
        *(float2*)&Op1[nt * 8 + 2 * lc] = make_float2(o[nt][2] * inv1, o[nt][3] * inv1);
    }
}

// ============================================================
// Kernel 3: per-head norm partial sums (deterministic 2-stage reduce).
// ============================================================
__global__ __launch_bounds__(256)
void norm_partial()
{
    const int c   = blockIdx.x;
    const int h   = blockIdx.y;
    const int tid = threadIdx.x;
    const int bt  = c * 256 + tid;
    const int b   = bt >> 11;
    const int t   = bt & 2047;

    const float* row = g_O + (size_t)((b * NH + h) * SEQ + t) * HD;
    float ss = 0.f;
    #pragma unroll
    for (int i = 0; i < 16; i++) {
        float4 v = *(const float4*)&row[i * 4];
        ss += v.x * v.x + v.y * v.y + v.z * v.z + v.w * v.w;
    }
    float nrm = sqrtf(ss);

    __shared__ float red[256];
    red[tid] = nrm;
    __syncthreads();
    for (int s = 128; s > 0; s >>= 1) {
        if (tid < s) red[tid] += red[tid + s];
        __syncthreads();
    }
    if (tid == 0) g_partial[h * 16 + c] = red[0];
}

// ============================================================
// Kernel 4: finalize per-head scale and fused output bias.
// ============================================================
__global__ void finalize(const float* __restrict__ gate,
                         const float* __restrict__ b_o)
{
    const int tid = threadIdx.x;   // 1024 threads
    if (tid < NH) {
        float s = 0.f;
        #pragma unroll
        for (int c = 0; c < 16; c++) s += g_partial[tid * 16 + c];
        float denom = fmaxf(s / (float)MROWS, 1e-5f);
        float g = fminf(fmaxf(gate[tid], 0.f), 1.f);
        g_scale[tid] = g / (denom * (float)NH);
    }
    float bsum = 0.f;
    #pragma unroll
    for (int h = 0; h < NH; h++) {
        float g = fminf(fmaxf(gate[h], 0.f), 1.f);
        bsum += g * b_o[h * EMB + tid];
    }
    g_bias[tid] = bsum / (float)NH;
}

// ============================================================
// Kernel 5: output projection GEMM (fp16 mma + ldmatrix).
// ============================================================
__global__ __launch_bounds__(256)
void out_gemm(const float* __restrict__ Wo, float* __restrict__ OUTP)
{
    __shared__ __half As[128][40];
    __shared__ __half Bs[32][136];

    const int m0   = blockIdx.y * 128;
    const int n0   = blockIdx.x * 128;
    const int tid  = threadIdx.x;
    const int warp = tid >> 5;
    const int lane = tid & 31;
    const int lr   = lane >> 2;
    const int lc   = lane & 3;
    const int wm   = (warp >> 2) * 64;
    const int wn   = (warp & 3) * 32;
    const int lrow = (lane & 7) + (lane & 8);
    const int lcol = (lane >> 1) & 8;

    float c[4][4][4];
    #pragma unroll
    for (int mt = 0; mt < 4; mt++)
        #pragma unroll
        for (int nt = 0; nt < 4; nt++)
            #pragma unroll
            for (int r = 0; r < 4; r++) c[mt][nt][r] = 0.f;

    for (int k0 = 0; k0 < EMB; k0 += 32) {
        const int hh = k0 >> 6;              // head constant within BK=32
        const float s = g_scale[hh];
        #pragma unroll
        for (int i = 0; i < 4; i++) {
            int f    = tid + i * 256;
            int arow = f >> 3;
            int ac   = (f & 7) * 4;
            int r    = m0 + arow;
            const float* src = &g_O[(size_t)(((r >> 11) * NH + hh) * SEQ + (r & 2047)) * HD
                                    + ((k0 & 63) + ac)];
            float4 v = *(const float4*)src;
            *(uint2*)&As[arow][ac] = make_uint2(h2(v.x * s, v.y * s), h2(v.z * s, v.w * s));
        }
        #pragma unroll
        for (int i = 0; i < 4; i++) {
            int f    = tid + i * 256;
            int brow = f >> 5;
            int bc   = (f & 31) * 4;
            float4 v = *(const float4*)&Wo[(size_t)(k0 + brow) * EMB + n0 + bc];
            *(uint2*)&Bs[brow][bc] = make_uint2(h2(v.x, v.y), h2(v.z, v.w));
        }
        __syncthreads();

        #pragma unroll
        for (int st = 0; st < 2; st++) {
            const int klo = st * 16;
            uint32_t a[4][4], bfr[2][4];
            #pragma unroll
            for (int mt = 0; mt < 4; mt++)
                ldsm_x4(a[mt][0], a[mt][1], a[mt][2], a[mt][3],
                        &As[wm + mt * 16 + lrow][klo + lcol]);
            #pragma unroll
            for (int p = 0; p < 2; p++)
                ldsm_x4t(bfr[p][0], bfr[p][1], bfr[p][2], bfr[p][3],
                         &Bs[klo + lrow][wn + p * 16 + lcol]);
            #pragma unroll
            for (int mt = 0; mt < 4; mt++)
                #pragma unroll
                for (int nt = 0; nt < 4; nt++)
                    mma16(c[mt][nt], a[mt], bfr[nt >> 1][(nt & 1) * 2],
                          bfr[nt >> 1][(nt & 1) * 2 + 1]);
        }
        __syncthreads();
    }

    #pragma unroll
    for (int mt = 0; mt < 4; mt++) {
        int row0 = m0 + wm + mt * 16 + lr;
        int row1 = row0 + 8;
        #pragma unroll
        for (int nt = 0; nt < 4; nt++) {
            int col = n0 + wn + nt * 8 + 2 * lc;
            float2 v0 = make_float2(c[mt][nt][0] + g_bias[col], c[mt][nt][1] + g_bias[col + 1]);
            float2 v1 = make_float2(c[mt][nt][2] + g_bias[col], c[mt][nt][3] + g_bias[col + 1]);
            *(float2*)&OUTP[(size_t)row0 * EMB + col] = v0;
            *(float2*)&OUTP[(size_t)row1 * EMB + col] = v1;
        }
    }
}

// ============================================================
extern "C" void kernel_launch(void* const* d_in, const int* in_sizes, int n_in,
                              void* d_out, int out_size)
{
    const float* X    = (const float*)d_in[0];
    const float* mask = (const float*)d_in[1];
    const float* Wq   = (const float*)d_in[2];
    const float* bq   = (const float*)d_in[3];
    const float* Wk   = (const float*)d_in[4];
    const float* bk   = (const float*)d_in[5];
    const float* Wv   = (const float*)d_in[6];
    const float* bv   = (const float*)d_in[7];
    const float* Wo   = (const float*)d_in[8];
    const float* bo   = (const float*)d_in[9];
    const float* gate = (const float*)d_in[10];
    float* out        = (float*)d_out;

    qkv_gemm    <<<dim3(EMB / 128, MROWS / 128, 3), 256>>>(X, Wq, bq, Wk, bk, Wv, bv);
    attn_kernel <<<dim3(SEQ / 64, NH, BATCH),       128>>>(mask);
    norm_partial<<<dim3(16, NH),                    256>>>();
    finalize    <<<1, EMB>>>(gate, bo);
    out_gemm    <<<dim3(EMB / 128, MROWS / 128),    256>>>(Wo, out);
}

// round 9
// speedup vs baseline: 1.6227x; 1.0153x over previous
#include <cuda_runtime.h>
#include <cuda_fp16.h>
#include <math.h>
#include <cstdint>

#define EMB   1024
#define HD    64
#define NH    16
#define SEQ   2048
#define BATCH 2
#define MROWS (BATCH*SEQ)          // 4096
#define QKV_ELEMS (BATCH*NH*SEQ*HD)

// ---- scratch (allocation-free: __device__ globals) ----
__device__ __half g_Q[QKV_ELEMS];
__device__ __half g_K[QKV_ELEMS];
__device__ __half g_V[QKV_ELEMS];
__device__ float  g_O[QKV_ELEMS];
__device__ float  g_partial[NH * 16];
__device__ float  g_scale[NH];
__device__ float  g_bias[EMB];

// ---- helpers ----
__device__ __forceinline__ uint32_t h2(float a, float b) {
    __half2 v = __floats2half2_rn(a, b);
    return *(uint32_t*)&v;
}
__device__ __forceinline__ uint32_t smem_u32(const void* p) {
    uint32_t a;
    asm("{ .reg .u64 t; cvta.to.shared.u64 t, %1; cvt.u32.u64 %0, t; }" : "=r"(a) : "l"(p));
    return a;
}
__device__ __forceinline__ void ldsm_x4(uint32_t& r0, uint32_t& r1, uint32_t& r2, uint32_t& r3,
                                        const void* p) {
    uint32_t a = smem_u32(p);
    asm volatile("ldmatrix.sync.aligned.m8n8.x4.shared.b16 {%0,%1,%2,%3},[%4];"
                 : "=r"(r0), "=r"(r1), "=r"(r2), "=r"(r3) : "r"(a));
}
__device__ __forceinline__ void ldsm_x4t(uint32_t& r0, uint32_t& r1, uint32_t& r2, uint32_t& r3,
                                         const void* p) {
    uint32_t a = smem_u32(p);
    asm volatile("ldmatrix.sync.aligned.m8n8.x4.trans.shared.b16 {%0,%1,%2,%3},[%4];"
                 : "=r"(r0), "=r"(r1), "=r"(r2), "=r"(r3) : "r"(a));
}
// D += A(16x16) * B(16x8); fp16 in, fp32 accum
__device__ __forceinline__ void mma16(float c[4], const uint32_t a[4],
                                      uint32_t b0, uint32_t b1) {
    asm volatile(
        "mma.sync.aligned.m16n8k16.row.col.f32.f16.f16.f32 "
        "{%0,%1,%2,%3},{%4,%5,%6,%7},{%8,%9},{%0,%1,%2,%3};"
        : "+f"(c[0]), "+f"(c[1]), "+f"(c[2]), "+f"(c[3])
        : "r"(a[0]), "r"(a[1]), "r"(a[2]), "r"(a[3]), "r"(b0), "r"(b1));
}

// ============================================================
// Kernel 1: QKV projection GEMM (fp16 mma + ldmatrix).
// ============================================================
__global__ __launch_bounds__(256)
void qkv_gemm(const float* __restrict__ X,
              const float* __restrict__ Wq, const float* __restrict__ bq,
              const float* __restrict__ Wk, const float* __restrict__ bk,
              const float* __restrict__ Wv, const float* __restrict__ bv)
{
    const int z = blockIdx.z;
    const float* W    = (z == 0) ? Wq : (z == 1) ? Wk : Wv;
    const float* bias = (z == 0) ? bq : (z == 1) ? bk : bv;
    __half* OUT       = (z == 0) ? g_Q : (z == 1) ? g_K : g_V;

    __shared__ __half As[128][40];    // m-major, k 32 + pad 8
    __shared__ __half Bs[32][136];    // k-major, n 128 + pad 8

    const int m0   = blockIdx.y * 128;
    const int n0   = blockIdx.x * 128;
    const int tid  = threadIdx.x;
    const int warp = tid >> 5;
    const int lane = tid & 31;
    const int lr   = lane >> 2;
    const int lc   = lane & 3;
    const int wm   = (warp >> 2) * 64;
    const int wn   = (warp & 3) * 32;
    const int lrow = (lane & 7) + (lane & 8);       // ldmatrix row-in-16
    const int lcol = (lane >> 1) & 8;               // ldmatrix col offset

    float c[4][4][4];
    #pragma unroll
    for (int mt = 0; mt < 4; mt++)
        #pragma unroll
        for (int nt = 0; nt < 4; nt++)
            #pragma unroll
            for (int r = 0; r < 4; r++) c[mt][nt][r] = 0.f;

    for (int k0 = 0; k0 < EMB; k0 += 32) {
        // A tile: 128 x 32
        #pragma unroll
        for (int i = 0; i < 4; i++) {
            int f    = tid + i * 256;
            int arow = f >> 3;
            int ac   = (f & 7) * 4;
            float4 v = *(const float4*)&X[(size_t)(m0 + arow) * EMB + k0 + ac];
            *(uint2*)&As[arow][ac] = make_uint2(h2(v.x, v.y), h2(v.z, v.w));
        }
        // B tile: 32 x 128 ; W element (k, c=(h,e)) at h*E*hd + k*hd + e
        #pragma unroll
        for (int i = 0; i < 4; i++) {
            int f    = tid + i * 256;
            int brow = f >> 5;
            int bc   = (f & 31) * 4;
            int cc   = n0 + bc;
            int hh   = cc >> 6;
            int e    = cc & 63;
            float4 v = *(const float4*)&W[(size_t)hh * (EMB * HD) + (size_t)(k0 + brow) * HD + e];
            *(uint2*)&Bs[brow][bc] = make_uint2(h2(v.x, v.y), h2(v.z, v.w));
        }
        __syncthreads();

        #pragma unroll
        for (int st = 0; st < 2; st++) {
            const int klo = st * 16;
            uint32_t a[4][4], bfr[2][4];
            #pragma unroll
            for (int mt = 0; mt < 4; mt++)
                ldsm_x4(a[mt][0], a[mt][1], a[mt][2], a[mt][3],
                        &As[wm + mt * 16 + lrow][klo + lcol]);
            #pragma unroll
            for (int p = 0; p < 2; p++)
                ldsm_x4t(bfr[p][0], bfr[p][1], bfr[p][2], bfr[p][3],
                         &Bs[klo + lrow][wn + p * 16 + lcol]);
            #pragma unroll
            for (int mt = 0; mt < 4; mt++)
                #pragma unroll
                for (int nt = 0; nt < 4; nt++)
                    mma16(c[mt][nt], a[mt], bfr[nt >> 1][(nt & 1) * 2],
                          bfr[nt >> 1][(nt & 1) * 2 + 1]);
        }
        __syncthreads();
    }

    // epilogue: remap to [B,H,T,hd] fp16, add bias
    #pragma unroll
    for (int mt = 0; mt < 4; mt++) {
        int row0 = m0 + wm + mt * 16 + lr;
        int row1 = row0 + 8;
        int b0i  = row0 >> 11, t0i = row0 & 2047;
        int b1i  = row1 >> 11, t1i = row1 & 2047;
        #pragma unroll
        for (int nt = 0; nt < 4; nt++) {
            int col = n0 + wn + nt * 8 + 2 * lc;
            int hh  = col >> 6;
            int e   = col & 63;
            uint32_t v0 = h2(c[mt][nt][0] + bias[col], c[mt][nt][1] + bias[col + 1]);
            uint32_t v1 = h2(c[mt][nt][2] + bias[col], c[mt][nt][3] + bias[col + 1]);
            *(uint32_t*)&OUT[(size_t)((b0i * NH + hh) * SEQ + t0i) * HD + e] = v0;
            *(uint32_t*)&OUT[(size_t)((b1i * NH + hh) * SEQ + t1i) * HD + e] = v1;
        }
    }
}

// ============================================================
// Kernel 2: flash attention per (b,h), fp16 mma + ldmatrix.
// ============================================================
__global__ __launch_bounds__(128)
void attn_kernel(const float* __restrict__ mask)
{
    __shared__ __half Ks[64][72];
    __shared__ __half Vs[64][72];

    const int mblk = blockIdx.x;
    const int h    = blockIdx.y;
    const int b    = blockIdx.z;
    const int tid  = threadIdx.x;
    const int warp = tid >> 5;
    const int lane = tid & 31;
    const int lr   = lane >> 2;
    const int lc   = lane & 3;
    const int wm   = warp * 16;
    const int lrow = (lane & 7) + (lane & 8);
    const int lcol = (lane >> 1) & 8;

    const __half* Q = g_Q + (size_t)(b * NH + h) * SEQ * HD;
    const __half* K = g_K + (size_t)(b * NH + h) * SEQ * HD;
    const __half* V = g_V + (size_t)(b * NH + h) * SEQ * HD;
    float*        O = g_O + (size_t)(b * NH + h) * SEQ * HD;

    const int t0 = mblk * 64;

    // Q fragments: 4 x k16 per warp (rows t0+wm+lr / +8), direct from gmem fp16
    uint32_t qa[4][4];
    {
        const __half* qp0 = Q + (size_t)(t0 + wm + lr) * HD;
        const __half* qp1 = qp0 + 8 * HD;
        #pragma unroll
        for (int q = 0; q < 4; q++) {
            int e = q * 16;
            qa[q][0] = *(const uint32_t*)&qp0[e + 2 * lc];
            qa[q][1] = *(const uint32_t*)&qp1[e + 2 * lc];
            qa[q][2] = *(const uint32_t*)&qp0[e + 2 * lc + 8];
            qa[q][3] = *(const uint32_t*)&qp1[e + 2 * lc + 8];
        }
    }

    float m_i[2] = {-INFINITY, -INFINITY};
    float l_i[2] = {0.f, 0.f};
    float o[8][4];
    #pragma unroll
    for (int nt = 0; nt < 8; nt++)
        #pragma unroll
        for (int r = 0; r < 4; r++) o[nt][r] = 0.f;

    const float* mrowA = mask + (size_t)(t0 + wm + lr) * SEQ;
    const float* mrowB = mrowA + (size_t)8 * SEQ;

    for (int s0 = 0; s0 < SEQ; s0 += 64) {
        __syncthreads();   // prev iter's smem reads complete

        // load K,V tiles (fp16, 8 halves = 16B per access)
        #pragma unroll
        for (int i = 0; i < 4; i++) {
            int f   = tid + i * 128;
            int row = f >> 3;
            int col = (f & 7) * 8;
            *(uint4*)&Ks[row][col] = *(const uint4*)&K[(size_t)(s0 + row) * HD + col];
            *(uint4*)&Vs[row][col] = *(const uint4*)&V[(size_t)(s0 + row) * HD + col];
        }
        __syncthreads();

        // S = Q K^T : per-warp 16x64
        float sc[8][4];
        #pragma unroll
        for (int nt = 0; nt < 8; nt++)
            #pragma unroll
            for (int r = 0; r < 4; r++) sc[nt][r] = 0.f;

        #pragma unroll
        for (int q = 0; q < 4; q++) {
            #pragma unroll
            for (int p = 0; p < 4; p++) {
                // Ks stored [s][e] = [n][k]; non-trans ldmatrix:
                //   r0 = (s0-7 , e0-7), r1 = (s8-15, e0-7),
                //   r2 = (s0-7 , e8-15), r3 = (s8-15, e8-15)
                // => b-pairs (k advances within a pair): (r0,r2) and (r1,r3)
                uint32_t r0, r1, r2, r3;
                ldsm_x4(r0, r1, r2, r3, &Ks[p * 16 + lrow][q * 16 + lcol]);
                mma16(sc[2 * p],     qa[q], r0, r2);
                mma16(sc[2 * p + 1], qa[q], r1, r3);
            }
        }

        // scale + mask
        #pragma unroll
        for (int nt = 0; nt < 8; nt++) {
            float2 mv0 = *(const float2*)&mrowA[s0 + nt * 8 + 2 * lc];
            float2 mv1 = *(const float2*)&mrowB[s0 + nt * 8 + 2 * lc];
            sc[nt][0] = sc[nt][0] * 0.125f + mv0.x;
            sc[nt][1] = sc[nt][1] * 0.125f + mv0.y;
            sc[nt][2] = sc[nt][2] * 0.125f + mv1.x;
            sc[nt][3] = sc[nt][3] * 0.125f + mv1.y;
        }

        // online softmax, two row-halves per thread
        #pragma unroll
        for (int half = 0; half < 2; half++) {
            float rm = -INFINITY;
            #pragma unroll
            for (int nt = 0; nt < 8; nt++)
                rm = fmaxf(rm, fmaxf(sc[nt][2 * half], sc[nt][2 * half + 1]));
            rm = fmaxf(rm, __shfl_xor_sync(0xffffffffu, rm, 1));
            rm = fmaxf(rm, __shfl_xor_sync(0xffffffffu, rm, 2));
            float mnew = fmaxf(m_i[half], rm);
            float corr = __expf(m_i[half] - mnew);
            float rs = 0.f;
            #pragma unroll
            for (int nt = 0; nt < 8; nt++) {
                float p0 = __expf(sc[nt][2 * half    ] - mnew);
                float p1 = __expf(sc[nt][2 * half + 1] - mnew);
                sc[nt][2 * half] = p0;
                sc[nt][2 * half + 1] = p1;
                rs += p0 + p1;
            }
            rs += __shfl_xor_sync(0xffffffffu, rs, 1);
            rs += __shfl_xor_sync(0xffffffffu, rs, 2);
            l_i[half] = l_i[half] * corr + rs;
            m_i[half] = mnew;
            #pragma unroll
            for (int nt = 0; nt < 8; nt++) {
                o[nt][2 * half] *= corr;
                o[nt][2 * half + 1] *= corr;
            }
        }

        // O += P V ; P taken straight from sc registers (C-frag == A-frag layout)
        #pragma unroll
        for (int q = 0; q < 4; q++) {
            uint32_t pa[4];
            pa[0] = h2(sc[2 * q][0], sc[2 * q][1]);
            pa[1] = h2(sc[2 * q][2], sc[2 * q][3]);
            pa[2] = h2(sc[2 * q + 1][0], sc[2 * q + 1][1]);
            pa[3] = h2(sc[2 * q + 1][2], sc[2 * q + 1][3]);
            #pragma unroll
            for (int p = 0; p < 4; p++) {
                // Vs stored [s][e] = [k][n]; trans ldmatrix: k advances r0->r1
                uint32_t b0a, b1a, b0b, b1b;
                ldsm_x4t(b0a, b1a, b0b, b1b, &Vs[q * 16 + lrow][p * 16 + lcol]);
                mma16(o[2 * p],     pa, b0a, b1a);
                mma16(o[2 * p + 1], pa, b0b, b1b);
            }
        }
    }

    // finalize: divide by l, write raw O fp32 (norm folded in later)
    float inv0 = 1.f / l_i[0];
    float inv1 = 1.f / l_i[1];
    float* Op0 = O + (size_t)(t0 + wm + lr) * HD;
    float* Op1 = Op0 + 8 * HD;
    #pragma unroll
    for (int nt = 0; nt < 8; nt++) {
        *(float2*)&Op0[nt * 8 + 2 * lc] = make_float2(o[nt][0] * inv0, o[nt][1] * inv0);
        *(float2*)&Op1[nt * 8 + 2 * lc] = make_float2(o[nt][2] * inv1, o[nt][3] * inv1);
    }
}

// ============================================================
// Kernel 3: per-head norm partial sums (deterministic 2-stage reduce).
// ============================================================
__global__ __launch_bounds__(256)
void norm_partial()
{
    const int c   = blockIdx.x;
    const int h   = blockIdx.y;
    const int tid = threadIdx.x;
    const int bt  = c * 256 + tid;
    const int b   = bt >> 11;
    const int t   = bt & 2047;

    const float* row = g_O + (size_t)((b * NH + h) * SEQ + t) * HD;
    float ss = 0.f;
    #pragma unroll
    for (int i = 0; i < 16; i++) {
        float4 v = *(const float4*)&row[i * 4];
        ss += v.x * v.x + v.y * v.y + v.z * v.z + v.w * v.w;
    }
    float nrm = sqrtf(ss);

    __shared__ float red[256];
    red[tid] = nrm;
    __syncthreads();
    for (int s = 128; s > 0; s >>= 1) {
        if (tid < s) red[tid] += red[tid + s];
        __syncthreads();
    }
    if (tid == 0) g_partial[h * 16 + c] = red[0];
}

// ============================================================
// Kernel 4: finalize per-head scale and fused output bias.
// ============================================================
__global__ void finalize(const float* __restrict__ gate,
                         const float* __restrict__ b_o)
{
    const int tid = threadIdx.x;   // 1024 threads
    if (tid < NH) {
        float s = 0.f;
        #pragma unroll
        for (int c = 0; c < 16; c++) s += g_partial[tid * 16 + c];
        float denom = fmaxf(s / (float)MROWS, 1e-5f);
        float g = fminf(fmaxf(gate[tid], 0.f), 1.f);
        g_scale[tid] = g / (denom * (float)NH);
    }
    float bsum = 0.f;
    #pragma unroll
    for (int h = 0; h < NH; h++) {
        float g = fminf(fmaxf(gate[h], 0.f), 1.f);
        bsum += g * b_o[h * EMB + tid];
    }
    g_bias[tid] = bsum / (float)NH;
}

// ============================================================
// Kernel 5: output projection GEMM (fp16 mma + ldmatrix).
// ============================================================
__global__ __launch_bounds__(256)
void out_gemm(const float* __restrict__ Wo, float* __restrict__ OUTP)
{
    __shared__ __half As[128][40];
    __shared__ __half Bs[32][136];

    const int m0   = blockIdx.y * 128;
    const int n0   = blockIdx.x * 128;
    const int tid  = threadIdx.x;
    const int warp = tid >> 5;
    const int lane = tid & 31;
    const int lr   = lane >> 2;
    const int lc   = lane & 3;
    const int wm   = (warp >> 2) * 64;
    const int wn   = (warp & 3) * 32;
    const int lrow = (lane & 7) + (lane & 8);
    const int lcol = (lane >> 1) & 8;

    float c[4][4][4];
    #pragma unroll
    for (int mt = 0; mt < 4; mt++)
        #pragma unroll
        for (int nt = 0; nt < 4; nt++)
            #pragma unroll
            for (int r = 0; r < 4; r++) c[mt][nt][r] = 0.f;

    for (int k0 = 0; k0 < EMB; k0 += 32) {
        const int hh = k0 >> 6;              // head constant within BK=32
        const float s = g_scale[hh];
        #pragma unroll
        for (int i = 0; i < 4; i++) {
            int f    = tid + i * 256;
            int arow = f >> 3;
            int ac   = (f & 7) * 4;
            int r    = m0 + arow;
            const float* src = &g_O[(size_t)(((r >> 11) * NH + hh) * SEQ + (r & 2047)) * HD
                                    + ((k0 & 63) + ac)];
            float4 v = *(const float4*)src;
            *(uint2*)&As[arow][ac] = make_uint2(h2(v.x * s, v.y * s), h2(v.z * s, v.w * s));
        }
        #pragma unroll
        for (int i = 0; i < 4; i++) {
            int f    = tid + i * 256;
            int brow = f >> 5;
            int bc   = (f & 31) * 4;
            float4 v = *(const float4*)&Wo[(size_t)(k0 + brow) * EMB + n0 + bc];
            *(uint2*)&Bs[brow][bc] = make_uint2(h2(v.x, v.y), h2(v.z, v.w));
        }
        __syncthreads();

        #pragma unroll
        for (int st = 0; st < 2; st++) {
            const int klo = st * 16;
            uint32_t a[4][4], bfr[2][4];
            #pragma unroll
            for (int mt = 0; mt < 4; mt++)
                ldsm_x4(a[mt][0], a[mt][1], a[mt][2], a[mt][3],
                        &As[wm + mt * 16 + lrow][klo + lcol]);
            #pragma unroll
            for (int p = 0; p < 2; p++)
                ldsm_x4t(bfr[p][0], bfr[p][1], bfr[p][2], bfr[p][3],
                         &Bs[klo + lrow][wn + p * 16 + lcol]);
            #pragma unroll
            for (int mt = 0; mt < 4; mt++)
                #pragma unroll
                for (int nt = 0; nt < 4; nt++)
                    mma16(c[mt][nt], a[mt], bfr[nt >> 1][(nt & 1) * 2],
                          bfr[nt >> 1][(nt & 1) * 2 + 1]);
        }
        __syncthreads();
    }

    #pragma unroll
    for (int mt = 0; mt < 4; mt++) {
        int row0 = m0 + wm + mt * 16 + lr;
        int row1 = row0 + 8;
        #pragma unroll
        for (int nt = 0; nt < 4; nt++) {
            int col = n0 + wn + nt * 8 + 2 * lc;
            float2 v0 = make_float2(c[mt][nt][0] + g_bias[col], c[mt][nt][1] + g_bias[col + 1]);
            float2 v1 = make_float2(c[mt][nt][2] + g_bias[col], c[mt][nt][3] + g_bias[col + 1]);
            *(float2*)&OUTP[(size_t)row0 * EMB + col] = v0;
            *(float2*)&OUTP[(size_t)row1 * EMB + col] = v1;
        }
    }
}

// ============================================================
extern "C" void kernel_launch(void* const* d_in, const int* in_sizes, int n_in,
                              void* d_out, int out_size)
{
    const float* X    = (const float*)d_in[0];
    const float* mask = (const float*)d_in[1];
    const float* Wq   = (const float*)d_in[2];
    const float* bq   = (const float*)d_in[3];
    const float* Wk   = (const float*)d_in[4];
    const float* bk   = (const float*)d_in[5];
    const float* Wv   = (const float*)d_in[6];
    const float* bv   = (const float*)d_in[7];
    const float* Wo   = (const float*)d_in[8];
    const float* bo   = (const float*)d_in[9];
    const float* gate = (const float*)d_in[10];
    float* out        = (float*)d_out;

    qkv_gemm    <<<dim3(EMB / 128, MROWS / 128, 3), 256>>>(X, Wq, bq, Wk, bk, Wv, bv);
    attn_kernel <<<dim3(SEQ / 64, NH, BATCH),       128>>>(mask);
    norm_partial<<<dim3(16, NH),                    256>>>();
    finalize    <<<1, EMB>>>(gate, bo);
    out_gemm    <<<dim3(EMB / 128, MROWS / 128),    256>>>(Wo, out);
}